// round 10
// baseline (speedup 1.0000x reference)
#include <cuda_runtime.h>
#include <cuda_bf16.h>
#include <cstdint>

#define DIM   128
#define MAXN  50000
#define MAXDEG 64
typedef unsigned long long ull;

// ---------------------------------------------------------------------------
// Device globals (no allocation allowed)
// ---------------------------------------------------------------------------
__device__ __align__(16) int   g_deg[MAXN];
__device__ __align__(16) int   g_elist[MAXN * MAXDEG];       // 12.8 MB
__device__ __align__(16) __nv_bfloat16 g_whi[128 * 256];     // W_cat hi, [n][k]
__device__ __align__(16) __nv_bfloat16 g_wlo[128 * 256];     // W_cat lo, [n][k]
__device__ int g_is64;

__device__ __forceinline__ uint32_t smem_u32(const void* p) {
    uint32_t a;
    asm("{ .reg .u64 t; cvta.to.shared.u64 t, %1; cvt.u32.u64 %0, t; }" : "=r"(a) : "l"(p));
    return a;
}
__device__ __forceinline__ void ldm4(uint32_t* r, uint32_t addr) {
    asm volatile("ldmatrix.sync.aligned.m8n8.x4.shared.b16 {%0,%1,%2,%3}, [%4];"
                 : "=r"(r[0]), "=r"(r[1]), "=r"(r[2]), "=r"(r[3]) : "r"(addr));
}
__device__ __forceinline__ void mma16816(float* c, const uint32_t* a, uint32_t b0, uint32_t b1) {
    asm volatile(
        "mma.sync.aligned.m16n8k16.row.col.f32.bf16.bf16.f32 "
        "{%0,%1,%2,%3}, {%4,%5,%6,%7}, {%8,%9}, {%0,%1,%2,%3};"
        : "+f"(c[0]), "+f"(c[1]), "+f"(c[2]), "+f"(c[3])
        : "r"(a[0]), "r"(a[1]), "r"(a[2]), "r"(a[3]), "r"(b0), "r"(b1));
}
__device__ __forceinline__ uint32_t pkbf(__nv_bfloat16 a, __nv_bfloat16 b) {
    __nv_bfloat162 t = __halves2bfloat162(a, b);
    return *reinterpret_cast<uint32_t*>(&t);
}

// ---------------------------------------------------------------------------
// Kernel 0: detect edge_index dtype
// ---------------------------------------------------------------------------
__global__ void detect_dtype_kernel(const void* ei_raw, int E, int N) {
    __shared__ int ok;
    if (threadIdx.x == 0) ok = 1;
    __syncthreads();
    const long long* e64 = (const long long*)ei_raw;
    int probe = (E < 1024) ? E : 1024;
    for (int i = threadIdx.x; i < probe; i += blockDim.x) {
        long long v = e64[i];
        if (v < 0 || v >= (long long)N) atomicExch(&ok, 0);
    }
    __syncthreads();
    if (threadIdx.x == 0) g_is64 = ok;
}

// ---------------------------------------------------------------------------
// Kernel 1: zero degree counters
// ---------------------------------------------------------------------------
__global__ void zero_kernel(int N) {
    int i = blockIdx.x * blockDim.x + threadIdx.x;
    if (i < N) g_deg[i] = 0;
}

// ---------------------------------------------------------------------------
// Kernel 2: W prep — W_cat[n][k] (k<128: W_l, else W_r), bf16 hi/lo split.
// ---------------------------------------------------------------------------
__global__ void wprep_kernel(const float* __restrict__ Wl, const float* __restrict__ Wr) {
    int i = blockIdx.x * blockDim.x + threadIdx.x;
    if (i >= 128 * 256) return;
    int n = i >> 8, k = i & 255;
    float v = (k < 128) ? Wl[n * 128 + k] : Wr[n * 128 + (k - 128)];
    __nv_bfloat16 h  = __float2bfloat16(v);
    __nv_bfloat16 lo = __float2bfloat16(v - __bfloat162float(h));
    g_whi[i] = h;
    g_wlo[i] = lo;
}

// ---------------------------------------------------------------------------
// Kernel 3: build per-node edge lists — 1 edge/thread (proven fastest; the
// 4-edge batched variant dropped occupancy and regressed).
// ---------------------------------------------------------------------------
__global__ void build_kernel(const void* __restrict__ ei_raw, int E, int N) {
    int e = blockIdx.x * blockDim.x + threadIdx.x;
    if (e >= E) return;
    long long s, d;
    if (g_is64) {
        const long long* ei = (const long long*)ei_raw;
        s = __ldg(&ei[e]);  d = __ldg(&ei[E + e]);
    } else {
        const int* ei = (const int*)ei_raw;
        s = __ldg(&ei[e]);  d = __ldg(&ei[E + e]);
    }
    if ((ull)s >= (ull)N || (ull)d >= (ull)N) return;
    int pos = atomicAdd(&g_deg[(int)d], 1);
    if (pos < MAXDEG) g_elist[(int)d * MAXDEG + pos] = (int)s;
}

// ---------------------------------------------------------------------------
// Kernel 4: FUSED pull + mma.sync bf16 GEMM (3-term split) + bias + LN + ReLU.
// Mean chunks (kt=0,1): A tile filled by gathering neighbor slices directly
// (half-warp per node, 16 lanes x float4 = 64 floats of the row), averaged,
// split to bf16 hi/lo in-flight. No g_agg array at all.
// x chunks (kt=2,3): direct copy-convert as before.
// smem 76.3KB -> 2 CTAs/SM (gather phase of one CTA hides under MMA of other).
// ---------------------------------------------------------------------------
#define APITCH 144            // bytes per smem row (72 bf16)
#define S_AHI  0
#define S_ALO  18432
#define S_BHI  36864
#define S_BLO  55296
#define S_SINV 73728
#define S_BIAS 74240
#define S_GAM  74752
#define S_BET  75264
#define S_DEG  75776          // int deg per row
#define SMEM_TOT 76288
#define S_STAGE 0
#define SPITCH 132

extern "C" __global__ void __launch_bounds__(256, 2)
gemm_mma_kernel(const float* __restrict__ x,
                const float* __restrict__ bl,
                const float* __restrict__ gamma,
                const float* __restrict__ beta,
                float* __restrict__ out, int N) {
    extern __shared__ char dsm[];
    uint32_t sb = smem_u32(dsm);
    int tid = threadIdx.x;
    int w = tid >> 5, l = tid & 31;
    int wr = w >> 1, wc = w & 1;            // warp tile: rows wr*32, cols wc*64
    int row0 = blockIdx.x * 128;

    if (tid < 128) {
        int g = row0 + tid;
        int dg = (g < N) ? g_deg[g] : 0;
        if (dg > MAXDEG) dg = MAXDEG;
        ((int*)(dsm + S_DEG))[tid]    = dg;
        ((float*)(dsm + S_SINV))[tid] = 1.f / fmaxf((float)dg, 1.f);
        ((float*)(dsm + S_BIAS))[tid] = bl[tid];
        ((float*)(dsm + S_GAM))[tid]  = gamma[tid];
        ((float*)(dsm + S_BET))[tid]  = beta[tid];
    }

    float acc[2][8][4];
#pragma unroll
    for (int a = 0; a < 2; ++a)
#pragma unroll
        for (int b = 0; b < 8; ++b)
#pragma unroll
            for (int c = 0; c < 4; ++c) acc[a][b][c] = 0.f;

    const float*  sInvS = (const float*)(dsm + S_SINV);
    const int*    sDegS = (const int*)(dsm + S_DEG);
    const float4* x4g   = reinterpret_cast<const float4*>(x);

    for (int kt = 0; kt < 4; ++kt) {                 // 4 chunks of K=64
        bool isMean = (kt < 2);
        int kb4 = (kt & 1) * 16;                     // float4 offset within row
        int kw  = kt * 64;                           // k offset within W (256 wide)
        __syncthreads();

        if (isMean) {
            // ---- A fill via fused pull: half-warp per node ----
            int hw = l >> 4, c = l & 15;
            uint32_t hmask = 0xFFFFu << (hw * 16);
#pragma unroll 1
            for (int i = 0; i < 8; ++i) {
                int r = w * 16 + i * 2 + hw;
                int deg = sDegS[r];
                const int* lst = g_elist + (size_t)(row0 + r) * MAXDEG;
                float4 a4 = make_float4(0.f, 0.f, 0.f, 0.f);
                for (int jb = 0; jb < deg; jb += 16) {
                    int myn = (jb + c < deg) ? __ldg(lst + jb + c) : 0;
                    int m = deg - jb; if (m > 16) m = 16;
                    int j = 0;
                    for (; j + 2 <= m; j += 2) {
                        int s0 = __shfl_sync(hmask, myn, j, 16);
                        int s1 = __shfl_sync(hmask, myn, j + 1, 16);
                        float4 v0 = __ldg(&x4g[(size_t)s0 * 32 + kb4 + c]);
                        float4 v1 = __ldg(&x4g[(size_t)s1 * 32 + kb4 + c]);
                        a4.x += v0.x + v1.x; a4.y += v0.y + v1.y;
                        a4.z += v0.z + v1.z; a4.w += v0.w + v1.w;
                    }
                    if (j < m) {
                        int s0 = __shfl_sync(hmask, myn, j, 16);
                        float4 v0 = __ldg(&x4g[(size_t)s0 * 32 + kb4 + c]);
                        a4.x += v0.x; a4.y += v0.y; a4.z += v0.z; a4.w += v0.w;
                    }
                }
                float iv = sInvS[r];
                a4.x *= iv; a4.y *= iv; a4.z *= iv; a4.w *= iv;
                __nv_bfloat16 h0 = __float2bfloat16(a4.x), h1 = __float2bfloat16(a4.y);
                __nv_bfloat16 h2 = __float2bfloat16(a4.z), h3 = __float2bfloat16(a4.w);
                __nv_bfloat16 e0 = __float2bfloat16(a4.x - __bfloat162float(h0));
                __nv_bfloat16 e1 = __float2bfloat16(a4.y - __bfloat162float(h1));
                __nv_bfloat16 e2 = __float2bfloat16(a4.z - __bfloat162float(h2));
                __nv_bfloat16 e3 = __float2bfloat16(a4.w - __bfloat162float(h3));
                int off = r * APITCH + c * 8;
                *(ull*)(dsm + S_AHI + off) = (ull)pkbf(h0, h1) | ((ull)pkbf(h2, h3) << 32);
                *(ull*)(dsm + S_ALO + off) = (ull)pkbf(e0, e1) | ((ull)pkbf(e2, e3) << 32);
            }
        } else {
            // ---- A fill: direct copy-convert from x ----
            for (int i = tid; i < 128 * 16; i += 256) {
                int r = i >> 4, q = i & 15;
                int g = row0 + r;
                float4 v = make_float4(0.f, 0.f, 0.f, 0.f);
                if (g < N)
                    v = __ldg(&x4g[(size_t)g * 32 + kb4 + q]);
                __nv_bfloat16 h0 = __float2bfloat16(v.x), h1 = __float2bfloat16(v.y);
                __nv_bfloat16 h2 = __float2bfloat16(v.z), h3 = __float2bfloat16(v.w);
                __nv_bfloat16 e0 = __float2bfloat16(v.x - __bfloat162float(h0));
                __nv_bfloat16 e1 = __float2bfloat16(v.y - __bfloat162float(h1));
                __nv_bfloat16 e2 = __float2bfloat16(v.z - __bfloat162float(h2));
                __nv_bfloat16 e3 = __float2bfloat16(v.w - __bfloat162float(h3));
                int off = r * APITCH + q * 8;
                *(ull*)(dsm + S_AHI + off) = (ull)pkbf(h0, h1) | ((ull)pkbf(h2, h3) << 32);
                *(ull*)(dsm + S_ALO + off) = (ull)pkbf(e0, e1) | ((ull)pkbf(e2, e3) << 32);
            }
        }
        // ---- B fill: 128 n-rows x 8 uint4 ----
        for (int i = tid; i < 128 * 8; i += 256) {
            int n = i >> 3, s = i & 7;
            uint4 vh = *((const uint4*)(g_whi + n * 256 + kw) + s);
            uint4 vl = *((const uint4*)(g_wlo + n * 256 + kw) + s);
            *(uint4*)(dsm + S_BHI + n * APITCH + s * 16) = vh;
            *(uint4*)(dsm + S_BLO + n * APITCH + s * 16) = vl;
        }
        __syncthreads();

        // ---- compute: 4 k16 steps ----
#pragma unroll
        for (int ks = 0; ks < 4; ++ks) {
            int lrow = (l & 7) + (l & 8);
            int lcol = ks * 16 + ((l & 16) ? 8 : 0);
            uint32_t ah[2][4], al[2][4];
#pragma unroll
            for (int mf = 0; mf < 2; ++mf) {
                int row = wr * 32 + mf * 16 + lrow;
                uint32_t addr = sb + S_AHI + row * APITCH + lcol * 2;
                ldm4(ah[mf], addr);
                ldm4(al[mf], addr + (S_ALO - S_AHI));
            }
#pragma unroll
            for (int nb = 0; nb < 4; ++nb) {
                int n = wc * 64 + nb * 16 + lrow;
                uint32_t baddr = sb + S_BHI + n * APITCH + lcol * 2;
                uint32_t bh[4], bo[4];
                ldm4(bh, baddr);
                ldm4(bo, baddr + (S_BLO - S_BHI));
#pragma unroll
                for (int mf = 0; mf < 2; ++mf) {
                    float* c0 = acc[mf][2 * nb];
                    float* c1 = acc[mf][2 * nb + 1];
                    mma16816(c0, ah[mf], bh[0], bh[2]);
                    mma16816(c1, ah[mf], bh[1], bh[3]);
                    mma16816(c0, al[mf], bh[0], bh[2]);
                    mma16816(c1, al[mf], bh[1], bh[3]);
                    mma16816(c0, ah[mf], bo[0], bo[2]);
                    mma16816(c1, ah[mf], bo[1], bo[3]);
                }
            }
        }
    }

    // ---- stage accumulators to smem (reuses tile region) ----
    __syncthreads();
    float* stag = (float*)(dsm + S_STAGE);
#pragma unroll
    for (int mf = 0; mf < 2; ++mf) {
#pragma unroll
        for (int nf = 0; nf < 8; ++nf) {
            int r = wr * 32 + mf * 16 + (l >> 2);
            int c = wc * 64 + nf * 8 + (l & 3) * 2;
            const float* cc = acc[mf][nf];
            *(float2*)(stag + r * SPITCH + c)       = make_float2(cc[0], cc[1]);
            *(float2*)(stag + (r + 8) * SPITCH + c) = make_float2(cc[2], cc[3]);
        }
    }
    __syncthreads();

    // ---- LN + ReLU: warp w handles rows w*16 .. w*16+15 ----
    const float4* biasS = (const float4*)(dsm + S_BIAS);
    const float4* gamS  = (const float4*)(dsm + S_GAM);
    const float4* betS  = (const float4*)(dsm + S_BET);
    float4 bb = biasS[l], gg = gamS[l], ee = betS[l];

    for (int r = w * 16; r < w * 16 + 16; ++r) {
        float4 v = *(const float4*)(stag + r * SPITCH + l * 4);
        v.x += bb.x; v.y += bb.y; v.z += bb.z; v.w += bb.w;
        float s = v.x + v.y + v.z + v.w;
#pragma unroll
        for (int m = 1; m < 32; m <<= 1) s += __shfl_xor_sync(0xffffffffu, s, m);
        float mu = s * (1.0f / 128.0f);
        float dx = v.x - mu, dy = v.y - mu, dz = v.z - mu, dw = v.w - mu;
        float q = dx * dx + dy * dy + dz * dz + dw * dw;
#pragma unroll
        for (int m = 1; m < 32; m <<= 1) q += __shfl_xor_sync(0xffffffffu, q, m);
        float rstd = rsqrtf(q * (1.0f / 128.0f) + 1e-5f);

        int g = row0 + r;
        if (g < N) {
            float4 o;
            o.x = fmaxf(fmaf(dx * rstd, gg.x, ee.x), 0.f);
            o.y = fmaxf(fmaf(dy * rstd, gg.y, ee.y), 0.f);
            o.z = fmaxf(fmaf(dz * rstd, gg.z, ee.z), 0.f);
            o.w = fmaxf(fmaf(dw * rstd, gg.w, ee.w), 0.f);
            *(float4*)(out + (size_t)g * 128 + l * 4) = o;
        }
    }
}

// ---------------------------------------------------------------------------
// Launch
// ---------------------------------------------------------------------------
extern "C" void kernel_launch(void* const* d_in, const int* in_sizes, int n_in,
                              void* d_out, int out_size) {
    const float* x      = (const float*)d_in[0];
    const void*  ei     = d_in[1];
    const float* Wl     = (const float*)d_in[2];
    const float* bl     = (const float*)d_in[3];
    const float* Wr     = (const float*)d_in[4];
    const float* gamma  = (const float*)d_in[5];
    const float* beta   = (const float*)d_in[6];
    float* out          = (float*)d_out;

    int N = in_sizes[0] / DIM;
    int E = in_sizes[1] / 2;

    cudaFuncSetAttribute(gemm_mma_kernel, cudaFuncAttributeMaxDynamicSharedMemorySize, SMEM_TOT);

    detect_dtype_kernel<<<1, 256>>>(ei, E, N);
    zero_kernel<<<(N + 255) / 256, 256>>>(N);
    wprep_kernel<<<(128 * 256 + 255) / 256, 256>>>(Wl, Wr);
    build_kernel<<<(E + 255) / 256, 256>>>(ei, E, N);
    {
        int blocks = (N + 127) / 128;
        gemm_mma_kernel<<<blocks, 256, SMEM_TOT>>>(x, bl, gamma, beta, out, N);
    }
}

// round 11
// speedup vs baseline: 1.4562x; 1.4562x over previous
#include <cuda_runtime.h>
#include <cuda_bf16.h>
#include <cstdint>

#define DIM   128
#define MAXN  50000
#define NPAD  50176           // MAXN rounded up to multiple of 128 (pad rows)
#define MAXDEG 64
typedef unsigned long long ull;

// ---------------------------------------------------------------------------
// Device globals (no allocation allowed)
// ---------------------------------------------------------------------------
__device__ __align__(16) int   g_deg[MAXN];
__device__ __align__(16) int   g_elist[MAXN * MAXDEG];       // 12.8 MB
__device__ __align__(16) __nv_bfloat16 g_mhi[NPAD * 128];    // mean hi
__device__ __align__(16) __nv_bfloat16 g_mlo[NPAD * 128];    // mean lo
__device__ __align__(16) __nv_bfloat16 g_xhi[NPAD * 128];    // x hi
__device__ __align__(16) __nv_bfloat16 g_xlo[NPAD * 128];    // x lo
__device__ __align__(16) __nv_bfloat16 g_whi[128 * 256];     // W_cat hi, [n][k]
__device__ __align__(16) __nv_bfloat16 g_wlo[128 * 256];     // W_cat lo, [n][k]
__device__ int g_is64;

__device__ __forceinline__ uint32_t smem_u32(const void* p) {
    uint32_t a;
    asm("{ .reg .u64 t; cvta.to.shared.u64 t, %1; cvt.u32.u64 %0, t; }" : "=r"(a) : "l"(p));
    return a;
}
__device__ __forceinline__ void ldm4(uint32_t* r, uint32_t addr) {
    asm volatile("ldmatrix.sync.aligned.m8n8.x4.shared.b16 {%0,%1,%2,%3}, [%4];"
                 : "=r"(r[0]), "=r"(r[1]), "=r"(r[2]), "=r"(r[3]) : "r"(addr));
}
__device__ __forceinline__ void mma16816(float* c, const uint32_t* a, uint32_t b0, uint32_t b1) {
    asm volatile(
        "mma.sync.aligned.m16n8k16.row.col.f32.bf16.bf16.f32 "
        "{%0,%1,%2,%3}, {%4,%5,%6,%7}, {%8,%9}, {%0,%1,%2,%3};"
        : "+f"(c[0]), "+f"(c[1]), "+f"(c[2]), "+f"(c[3])
        : "r"(a[0]), "r"(a[1]), "r"(a[2]), "r"(a[3]), "r"(b0), "r"(b1));
}
__device__ __forceinline__ uint32_t pkbf(__nv_bfloat16 a, __nv_bfloat16 b) {
    __nv_bfloat162 t = __halves2bfloat162(a, b);
    return *reinterpret_cast<uint32_t*>(&t);
}
__device__ __forceinline__ ull split4(float4 v, ull& loOut) {
    __nv_bfloat16 h0 = __float2bfloat16(v.x), h1 = __float2bfloat16(v.y);
    __nv_bfloat16 h2 = __float2bfloat16(v.z), h3 = __float2bfloat16(v.w);
    __nv_bfloat16 e0 = __float2bfloat16(v.x - __bfloat162float(h0));
    __nv_bfloat16 e1 = __float2bfloat16(v.y - __bfloat162float(h1));
    __nv_bfloat16 e2 = __float2bfloat16(v.z - __bfloat162float(h2));
    __nv_bfloat16 e3 = __float2bfloat16(v.w - __bfloat162float(h3));
    loOut = (ull)pkbf(e0, e1) | ((ull)pkbf(e2, e3) << 32);
    return (ull)pkbf(h0, h1) | ((ull)pkbf(h2, h3) << 32);
}
__device__ __forceinline__ void cpa16(uint32_t smem, const void* g) {
    asm volatile("cp.async.ca.shared.global [%0], [%1], 16;" :: "r"(smem), "l"(g));
}
#define CPA_COMMIT() asm volatile("cp.async.commit_group;" ::: "memory")
#define CPA_WAIT0()  asm volatile("cp.async.wait_group 0;" ::: "memory")

// ---------------------------------------------------------------------------
// Kernel 0: detect edge_index dtype
// ---------------------------------------------------------------------------
__global__ void detect_dtype_kernel(const void* ei_raw, int E, int N) {
    __shared__ int ok;
    if (threadIdx.x == 0) ok = 1;
    __syncthreads();
    const long long* e64 = (const long long*)ei_raw;
    int probe = (E < 1024) ? E : 1024;
    for (int i = threadIdx.x; i < probe; i += blockDim.x) {
        long long v = e64[i];
        if (v < 0 || v >= (long long)N) atomicExch(&ok, 0);
    }
    __syncthreads();
    if (threadIdx.x == 0) g_is64 = ok;
}

// ---------------------------------------------------------------------------
// Kernel 1: zero degree counters
// ---------------------------------------------------------------------------
__global__ void zero_kernel(int N) {
    int i = blockIdx.x * blockDim.x + threadIdx.x;
    if (i < N) g_deg[i] = 0;
}

// ---------------------------------------------------------------------------
// Kernel 2a: W prep — bf16 hi/lo split of W_cat[n][k]
// ---------------------------------------------------------------------------
__global__ void wprep_kernel(const float* __restrict__ Wl, const float* __restrict__ Wr) {
    int i = blockIdx.x * blockDim.x + threadIdx.x;
    if (i >= 128 * 256) return;
    int n = i >> 8, k = i & 255;
    float v = (k < 128) ? Wl[n * 128 + k] : Wr[n * 128 + (k - 128)];
    __nv_bfloat16 h  = __float2bfloat16(v);
    __nv_bfloat16 lo = __float2bfloat16(v - __bfloat162float(h));
    g_whi[i] = h;
    g_wlo[i] = lo;
}

// ---------------------------------------------------------------------------
// Kernel 2b: x prep — split x rows to bf16 hi/lo (pad rows zeroed)
// ---------------------------------------------------------------------------
__global__ void xprep_kernel(const float* __restrict__ x, int N) {
    int i = blockIdx.x * blockDim.x + threadIdx.x;     // float4 chunk id
    if (i >= NPAD * 32) return;
    int n = i >> 5, q = i & 31;
    float4 v = make_float4(0.f, 0.f, 0.f, 0.f);
    if (n < N) v = __ldg(reinterpret_cast<const float4*>(x) + (size_t)n * 32 + q);
    ull lo, hi = split4(v, lo);
    ((ull*)g_xhi)[(size_t)n * 32 + q] = hi;
    ((ull*)g_xlo)[(size_t)n * 32 + q] = lo;
}

// ---------------------------------------------------------------------------
// Kernel 3: build per-node edge lists — 1 edge/thread (proven fastest)
// ---------------------------------------------------------------------------
__global__ void build_kernel(const void* __restrict__ ei_raw, int E, int N) {
    int e = blockIdx.x * blockDim.x + threadIdx.x;
    if (e >= E) return;
    long long s, d;
    if (g_is64) {
        const long long* ei = (const long long*)ei_raw;
        s = __ldg(&ei[e]);  d = __ldg(&ei[E + e]);
    } else {
        const int* ei = (const int*)ei_raw;
        s = __ldg(&ei[e]);  d = __ldg(&ei[E + e]);
    }
    if ((ull)s >= (ull)N || (ull)d >= (ull)N) return;
    int pos = atomicAdd(&g_deg[(int)d], 1);
    if (pos < MAXDEG) g_elist[(int)d * MAXDEG + pos] = (int)s;
}

// ---------------------------------------------------------------------------
// Kernel 4: pull aggregation — one warp per node; fp32 accumulate, then
// write mean as bf16 hi/lo (captures the fp32 mean to ~2^-16).
// Covers NPAD nodes so pad rows are zeroed.
// ---------------------------------------------------------------------------
__global__ void pull_kernel(const float* __restrict__ x, int N) {
    int node = blockIdx.x * (blockDim.x >> 5) + (threadIdx.x >> 5);
    if (node >= NPAD) return;
    int lane = threadIdx.x & 31;

    int deg = (node < N) ? g_deg[node] : 0;
    if (deg > MAXDEG) deg = MAXDEG;
    const int* lst = g_elist + (size_t)node * MAXDEG;
    const float4* x4 = reinterpret_cast<const float4*>(x);

    float4 acc = make_float4(0.f, 0.f, 0.f, 0.f);
    int j = 0;
    for (; j + 4 <= deg; j += 4) {
        int s0 = __ldg(lst + j),     s1 = __ldg(lst + j + 1);
        int s2 = __ldg(lst + j + 2), s3 = __ldg(lst + j + 3);
        float4 v0 = __ldg(&x4[(size_t)s0 * 32 + lane]);
        float4 v1 = __ldg(&x4[(size_t)s1 * 32 + lane]);
        float4 v2 = __ldg(&x4[(size_t)s2 * 32 + lane]);
        float4 v3 = __ldg(&x4[(size_t)s3 * 32 + lane]);
        acc.x += v0.x + v1.x + v2.x + v3.x;
        acc.y += v0.y + v1.y + v2.y + v3.y;
        acc.z += v0.z + v1.z + v2.z + v3.z;
        acc.w += v0.w + v1.w + v2.w + v3.w;
    }
    for (; j < deg; ++j) {
        int s0 = __ldg(lst + j);
        float4 v0 = __ldg(&x4[(size_t)s0 * 32 + lane]);
        acc.x += v0.x; acc.y += v0.y; acc.z += v0.z; acc.w += v0.w;
    }
    float inv = 1.f / fmaxf((float)deg, 1.f);
    acc.x *= inv; acc.y *= inv; acc.z *= inv; acc.w *= inv;
    ull lo, hi = split4(acc, lo);
    ((ull*)g_mhi)[(size_t)node * 32 + lane] = hi;
    ((ull*)g_mlo)[(size_t)node * 32 + lane] = lo;
}

// ---------------------------------------------------------------------------
// Kernel 5: mma.sync bf16 GEMM (3-term split) + bias + LayerNorm + ReLU.
// All sources pre-split bf16 -> tile fills are pure 16B cp.async copies.
// K in 4 chunks of 64; smem 75.7KB -> 2 CTAs/SM.
// ---------------------------------------------------------------------------
#define APITCH 144            // bytes per smem row (72 bf16); 9x16B, co-prime w/ banks
#define S_AHI  0
#define S_ALO  18432
#define S_BHI  36864
#define S_BLO  55296
#define S_BIAS 73728
#define S_GAM  74240
#define S_BET  74752
#define SMEM_TOT 75264
#define S_STAGE 0
#define SPITCH 132

extern "C" __global__ void __launch_bounds__(256, 2)
gemm_mma_kernel(const float* __restrict__ bl,
                const float* __restrict__ gamma,
                const float* __restrict__ beta,
                float* __restrict__ out, int N) {
    extern __shared__ char dsm[];
    uint32_t sb = smem_u32(dsm);
    int tid = threadIdx.x;
    int w = tid >> 5, l = tid & 31;
    int wr = w >> 1, wc = w & 1;            // warp tile: rows wr*32, cols wc*64
    int row0 = blockIdx.x * 128;

    if (tid < 128) {
        ((float*)(dsm + S_BIAS))[tid] = bl[tid];
        ((float*)(dsm + S_GAM))[tid]  = gamma[tid];
        ((float*)(dsm + S_BET))[tid]  = beta[tid];
    }

    float acc[2][8][4];
#pragma unroll
    for (int a = 0; a < 2; ++a)
#pragma unroll
        for (int b = 0; b < 8; ++b)
#pragma unroll
            for (int c = 0; c < 4; ++c) acc[a][b][c] = 0.f;

    for (int kt = 0; kt < 4; ++kt) {                 // 4 chunks of K=64
        const __nv_bfloat16* srcHi = (kt < 2) ? g_mhi : g_xhi;
        const __nv_bfloat16* srcLo = (kt < 2) ? g_mlo : g_xlo;
        int koff = (kt & 1) * 64;                    // col offset within 128-wide row
        int kw   = kt * 64;                          // k offset within W (256 wide)
        __syncthreads();

        // ---- A fill: pure cp.async, 8 x 16B per row per tile ----
        for (int i = tid; i < 128 * 8; i += 256) {
            int r = i >> 3, q = i & 7;
            size_t gofs = (size_t)(row0 + r) * 128 + koff + q * 8;
            cpa16(sb + S_AHI + r * APITCH + q * 16, srcHi + gofs);
            cpa16(sb + S_ALO + r * APITCH + q * 16, srcLo + gofs);
        }
        // ---- B fill: pure cp.async ----
        for (int i = tid; i < 128 * 8; i += 256) {
            int n = i >> 3, s = i & 7;
            size_t gofs = (size_t)n * 256 + kw + s * 8;
            cpa16(sb + S_BHI + n * APITCH + s * 16, g_whi + gofs);
            cpa16(sb + S_BLO + n * APITCH + s * 16, g_wlo + gofs);
        }
        CPA_COMMIT();
        CPA_WAIT0();
        __syncthreads();

        // ---- compute: 4 k16 steps ----
#pragma unroll
        for (int ks = 0; ks < 4; ++ks) {
            int lrow = (l & 7) + (l & 8);
            int lcol = ks * 16 + ((l & 16) ? 8 : 0);
            uint32_t ah[2][4], al[2][4];
#pragma unroll
            for (int mf = 0; mf < 2; ++mf) {
                int row = wr * 32 + mf * 16 + lrow;
                uint32_t addr = sb + S_AHI + row * APITCH + lcol * 2;
                ldm4(ah[mf], addr);
                ldm4(al[mf], addr + (S_ALO - S_AHI));
            }
#pragma unroll
            for (int nb = 0; nb < 4; ++nb) {
                int n = wc * 64 + nb * 16 + lrow;
                uint32_t baddr = sb + S_BHI + n * APITCH + lcol * 2;
                uint32_t bh[4], bo[4];
                ldm4(bh, baddr);
                ldm4(bo, baddr + (S_BLO - S_BHI));
#pragma unroll
                for (int mf = 0; mf < 2; ++mf) {
                    float* c0 = acc[mf][2 * nb];
                    float* c1 = acc[mf][2 * nb + 1];
                    mma16816(c0, ah[mf], bh[0], bh[2]);
                    mma16816(c1, ah[mf], bh[1], bh[3]);
                    mma16816(c0, al[mf], bh[0], bh[2]);
                    mma16816(c1, al[mf], bh[1], bh[3]);
                    mma16816(c0, ah[mf], bo[0], bo[2]);
                    mma16816(c1, ah[mf], bo[1], bo[3]);
                }
            }
        }
    }

    // ---- stage accumulators to smem (reuses tile region) ----
    __syncthreads();
    float* stag = (float*)(dsm + S_STAGE);
#pragma unroll
    for (int mf = 0; mf < 2; ++mf) {
#pragma unroll
        for (int nf = 0; nf < 8; ++nf) {
            int r = wr * 32 + mf * 16 + (l >> 2);
            int c = wc * 64 + nf * 8 + (l & 3) * 2;
            const float* cc = acc[mf][nf];
            *(float2*)(stag + r * SPITCH + c)       = make_float2(cc[0], cc[1]);
            *(float2*)(stag + (r + 8) * SPITCH + c) = make_float2(cc[2], cc[3]);
        }
    }
    __syncthreads();

    // ---- LN + ReLU: warp w handles rows w*16 .. w*16+15 ----
    const float4* biasS = (const float4*)(dsm + S_BIAS);
    const float4* gamS  = (const float4*)(dsm + S_GAM);
    const float4* betS  = (const float4*)(dsm + S_BET);
    float4 bb = biasS[l], gg = gamS[l], ee = betS[l];

    for (int r = w * 16; r < w * 16 + 16; ++r) {
        float4 v = *(const float4*)(stag + r * SPITCH + l * 4);
        v.x += bb.x; v.y += bb.y; v.z += bb.z; v.w += bb.w;
        float s = v.x + v.y + v.z + v.w;
#pragma unroll
        for (int m = 1; m < 32; m <<= 1) s += __shfl_xor_sync(0xffffffffu, s, m);
        float mu = s * (1.0f / 128.0f);
        float dx = v.x - mu, dy = v.y - mu, dz = v.z - mu, dw = v.w - mu;
        float q = dx * dx + dy * dy + dz * dz + dw * dw;
#pragma unroll
        for (int m = 1; m < 32; m <<= 1) q += __shfl_xor_sync(0xffffffffu, q, m);
        float rstd = rsqrtf(q * (1.0f / 128.0f) + 1e-5f);

        int g = row0 + r;
        if (g < N) {
            float4 o;
            o.x = fmaxf(fmaf(dx * rstd, gg.x, ee.x), 0.f);
            o.y = fmaxf(fmaf(dy * rstd, gg.y, ee.y), 0.f);
            o.z = fmaxf(fmaf(dz * rstd, gg.z, ee.z), 0.f);
            o.w = fmaxf(fmaf(dw * rstd, gg.w, ee.w), 0.f);
            *(float4*)(out + (size_t)g * 128 + l * 4) = o;
        }
    }
}

// ---------------------------------------------------------------------------
// Launch
// ---------------------------------------------------------------------------
extern "C" void kernel_launch(void* const* d_in, const int* in_sizes, int n_in,
                              void* d_out, int out_size) {
    const float* x      = (const float*)d_in[0];
    const void*  ei     = d_in[1];
    const float* Wl     = (const float*)d_in[2];
    const float* bl     = (const float*)d_in[3];
    const float* Wr     = (const float*)d_in[4];
    const float* gamma  = (const float*)d_in[5];
    const float* beta   = (const float*)d_in[6];
    float* out          = (float*)d_out;

    int N = in_sizes[0] / DIM;
    int E = in_sizes[1] / 2;

    cudaFuncSetAttribute(gemm_mma_kernel, cudaFuncAttributeMaxDynamicSharedMemorySize, SMEM_TOT);

    detect_dtype_kernel<<<1, 256>>>(ei, E, N);
    zero_kernel<<<(N + 255) / 256, 256>>>(N);
    wprep_kernel<<<(128 * 256 + 255) / 256, 256>>>(Wl, Wr);
    xprep_kernel<<<(NPAD * 32 + 255) / 256, 256>>>(x, N);
    build_kernel<<<(E + 255) / 256, 256>>>(ei, E, N);
    {
        int blocks = (NPAD + 7) / 8;        // one warp per node incl. pad rows
        pull_kernel<<<blocks, 256>>>(x, N);
    }
    {
        int blocks = (N + 127) / 128;
        gemm_mma_kernel<<<blocks, 256, SMEM_TOT>>>(bl, gamma, beta, out, N);
    }
}

// round 12
// speedup vs baseline: 1.5594x; 1.0709x over previous
#include <cuda_runtime.h>
#include <cuda_bf16.h>
#include <cstdint>

#define DIM   128
#define MAXN  50000
#define NPAD  50176           // MAXN rounded up to multiple of 128 (pad rows)
#define MAXDEG 64
typedef unsigned long long ull;

// ---------------------------------------------------------------------------
// Device globals (no allocation allowed)
// ---------------------------------------------------------------------------
__device__ __align__(16) int   g_deg[MAXN];
__device__ __align__(16) int   g_elist[MAXN * MAXDEG];       // 12.8 MB
__device__ __align__(16) __nv_bfloat16 g_mhi[NPAD * 128];    // mean hi
__device__ __align__(16) __nv_bfloat16 g_mlo[NPAD * 128];    // mean lo
__device__ __align__(16) __nv_bfloat16 g_xhi[NPAD * 128];    // x hi
__device__ __align__(16) __nv_bfloat16 g_xlo[NPAD * 128];    // x lo
__device__ __align__(16) __nv_bfloat16 g_whi[128 * 256];     // W_cat hi, [n][k]
__device__ __align__(16) __nv_bfloat16 g_wlo[128 * 256];     // W_cat lo, [n][k]
__device__ int g_is64;

__device__ __forceinline__ uint32_t smem_u32(const void* p) {
    uint32_t a;
    asm("{ .reg .u64 t; cvta.to.shared.u64 t, %1; cvt.u32.u64 %0, t; }" : "=r"(a) : "l"(p));
    return a;
}
__device__ __forceinline__ void ldm4(uint32_t* r, uint32_t addr) {
    asm volatile("ldmatrix.sync.aligned.m8n8.x4.shared.b16 {%0,%1,%2,%3}, [%4];"
                 : "=r"(r[0]), "=r"(r[1]), "=r"(r[2]), "=r"(r[3]) : "r"(addr));
}
__device__ __forceinline__ void mma16816(float* c, const uint32_t* a, uint32_t b0, uint32_t b1) {
    asm volatile(
        "mma.sync.aligned.m16n8k16.row.col.f32.bf16.bf16.f32 "
        "{%0,%1,%2,%3}, {%4,%5,%6,%7}, {%8,%9}, {%0,%1,%2,%3};"
        : "+f"(c[0]), "+f"(c[1]), "+f"(c[2]), "+f"(c[3])
        : "r"(a[0]), "r"(a[1]), "r"(a[2]), "r"(a[3]), "r"(b0), "r"(b1));
}
__device__ __forceinline__ uint32_t pkbf(__nv_bfloat16 a, __nv_bfloat16 b) {
    __nv_bfloat162 t = __halves2bfloat162(a, b);
    return *reinterpret_cast<uint32_t*>(&t);
}
__device__ __forceinline__ ull split4(float4 v, ull& loOut) {
    __nv_bfloat16 h0 = __float2bfloat16(v.x), h1 = __float2bfloat16(v.y);
    __nv_bfloat16 h2 = __float2bfloat16(v.z), h3 = __float2bfloat16(v.w);
    __nv_bfloat16 e0 = __float2bfloat16(v.x - __bfloat162float(h0));
    __nv_bfloat16 e1 = __float2bfloat16(v.y - __bfloat162float(h1));
    __nv_bfloat16 e2 = __float2bfloat16(v.z - __bfloat162float(h2));
    __nv_bfloat16 e3 = __float2bfloat16(v.w - __bfloat162float(h3));
    loOut = (ull)pkbf(e0, e1) | ((ull)pkbf(e2, e3) << 32);
    return (ull)pkbf(h0, h1) | ((ull)pkbf(h2, h3) << 32);
}
__device__ __forceinline__ void cpa16(uint32_t smem, const void* g) {
    asm volatile("cp.async.ca.shared.global [%0], [%1], 16;" :: "r"(smem), "l"(g));
}
#define CPA_COMMIT() asm volatile("cp.async.commit_group;" ::: "memory")
#define CPA_WAIT0()  asm volatile("cp.async.wait_group 0;" ::: "memory")

// ---------------------------------------------------------------------------
// Kernel A (merged prep): detect dtype (block 0) + zero g_deg + W split.
// All independent elementwise work -> one launch.
// ---------------------------------------------------------------------------
__global__ void prep_kernel(const void* ei_raw, int E, int N,
                            const float* __restrict__ Wl, const float* __restrict__ Wr) {
    int i = blockIdx.x * blockDim.x + threadIdx.x;

    if (blockIdx.x == 0) {                 // dtype probe (256 threads)
        __shared__ int ok;
        if (threadIdx.x == 0) ok = 1;
        __syncthreads();
        const long long* e64 = (const long long*)ei_raw;
        int probe = (E < 1024) ? E : 1024;
        for (int j = threadIdx.x; j < probe; j += blockDim.x) {
            long long v = e64[j];
            if (v < 0 || v >= (long long)N) atomicExch(&ok, 0);
        }
        __syncthreads();
        if (threadIdx.x == 0) g_is64 = ok;
    }
    if (i < N) g_deg[i] = 0;
    if (i < 128 * 256) {
        int n = i >> 8, k = i & 255;
        float v = (k < 128) ? Wl[n * 128 + k] : Wr[n * 128 + (k - 128)];
        __nv_bfloat16 h  = __float2bfloat16(v);
        __nv_bfloat16 lo = __float2bfloat16(v - __bfloat162float(h));
        g_whi[i] = h;
        g_wlo[i] = lo;
    }
}

// ---------------------------------------------------------------------------
// Kernel B (merged): build edge lists (atomic/latency-bound) + x hi/lo split
// (bandwidth-bound). Disjoint resources -> grid-split fusion so they overlap.
// build blocks first (their atomic chains start early), xprep blocks behind.
// ---------------------------------------------------------------------------
#define BBLK(E) (((E) + 255) / 256)
#define XBLK    ((NPAD * 32 + 255) / 256)

__global__ void build_xprep_kernel(const void* __restrict__ ei_raw,
                                   const float* __restrict__ x, int E, int N,
                                   int buildBlocks) {
    if ((int)blockIdx.x < buildBlocks) {
        // ---- build: 1 edge/thread (proven fastest shape) ----
        int e = blockIdx.x * blockDim.x + threadIdx.x;
        if (e >= E) return;
        long long s, d;
        if (g_is64) {
            const long long* ei = (const long long*)ei_raw;
            s = __ldg(&ei[e]);  d = __ldg(&ei[E + e]);
        } else {
            const int* ei = (const int*)ei_raw;
            s = __ldg(&ei[e]);  d = __ldg(&ei[E + e]);
        }
        if ((ull)s >= (ull)N || (ull)d >= (ull)N) return;
        int pos = atomicAdd(&g_deg[(int)d], 1);
        if (pos < MAXDEG) g_elist[(int)d * MAXDEG + pos] = (int)s;
    } else {
        // ---- xprep: split x rows to bf16 hi/lo (pad rows zeroed) ----
        int i = (blockIdx.x - buildBlocks) * blockDim.x + threadIdx.x;
        if (i >= NPAD * 32) return;
        int n = i >> 5, q = i & 31;
        float4 v = make_float4(0.f, 0.f, 0.f, 0.f);
        if (n < N) v = __ldg(reinterpret_cast<const float4*>(x) + (size_t)n * 32 + q);
        ull lo, hi = split4(v, lo);
        ((ull*)g_xhi)[(size_t)n * 32 + q] = hi;
        ((ull*)g_xlo)[(size_t)n * 32 + q] = lo;
    }
}

// ---------------------------------------------------------------------------
// Kernel C: pull aggregation — one warp per node; fp32 accumulate; write
// mean as bf16 hi/lo. Covers NPAD so pad rows are zeroed.
// ---------------------------------------------------------------------------
__global__ void pull_kernel(const float* __restrict__ x, int N) {
    int node = blockIdx.x * (blockDim.x >> 5) + (threadIdx.x >> 5);
    if (node >= NPAD) return;
    int lane = threadIdx.x & 31;

    int deg = (node < N) ? g_deg[node] : 0;
    if (deg > MAXDEG) deg = MAXDEG;
    const int* lst = g_elist + (size_t)node * MAXDEG;
    const float4* x4 = reinterpret_cast<const float4*>(x);

    float4 acc = make_float4(0.f, 0.f, 0.f, 0.f);
    int j = 0;
    for (; j + 4 <= deg; j += 4) {
        int s0 = __ldg(lst + j),     s1 = __ldg(lst + j + 1);
        int s2 = __ldg(lst + j + 2), s3 = __ldg(lst + j + 3);
        float4 v0 = __ldg(&x4[(size_t)s0 * 32 + lane]);
        float4 v1 = __ldg(&x4[(size_t)s1 * 32 + lane]);
        float4 v2 = __ldg(&x4[(size_t)s2 * 32 + lane]);
        float4 v3 = __ldg(&x4[(size_t)s3 * 32 + lane]);
        acc.x += v0.x + v1.x + v2.x + v3.x;
        acc.y += v0.y + v1.y + v2.y + v3.y;
        acc.z += v0.z + v1.z + v2.z + v3.z;
        acc.w += v0.w + v1.w + v2.w + v3.w;
    }
    for (; j < deg; ++j) {
        int s0 = __ldg(lst + j);
        float4 v0 = __ldg(&x4[(size_t)s0 * 32 + lane]);
        acc.x += v0.x; acc.y += v0.y; acc.z += v0.z; acc.w += v0.w;
    }
    float inv = 1.f / fmaxf((float)deg, 1.f);
    acc.x *= inv; acc.y *= inv; acc.z *= inv; acc.w *= inv;
    ull lo, hi = split4(acc, lo);
    ((ull*)g_mhi)[(size_t)node * 32 + lane] = hi;
    ((ull*)g_mlo)[(size_t)node * 32 + lane] = lo;
}

// ---------------------------------------------------------------------------
// Kernel D: mma.sync bf16 GEMM (3-term split) + bias + LayerNorm + ReLU.
// All sources pre-split bf16 -> tile fills are pure 16B cp.async copies.
// K in 4 chunks of 64; smem 73.5KB -> 2 CTAs/SM.
// ---------------------------------------------------------------------------
#define APITCH 144            // bytes per smem row (72 bf16); 9x16B, co-prime w/ banks
#define S_AHI  0
#define S_ALO  18432
#define S_BHI  36864
#define S_BLO  55296
#define S_BIAS 73728
#define S_GAM  74240
#define S_BET  74752
#define SMEM_TOT 75264
#define S_STAGE 0
#define SPITCH 132

extern "C" __global__ void __launch_bounds__(256, 2)
gemm_mma_kernel(const float* __restrict__ bl,
                const float* __restrict__ gamma,
                const float* __restrict__ beta,
                float* __restrict__ out, int N) {
    extern __shared__ char dsm[];
    uint32_t sb = smem_u32(dsm);
    int tid = threadIdx.x;
    int w = tid >> 5, l = tid & 31;
    int wr = w >> 1, wc = w & 1;            // warp tile: rows wr*32, cols wc*64
    int row0 = blockIdx.x * 128;

    if (tid < 128) {
        ((float*)(dsm + S_BIAS))[tid] = bl[tid];
        ((float*)(dsm + S_GAM))[tid]  = gamma[tid];
        ((float*)(dsm + S_BET))[tid]  = beta[tid];
    }

    float acc[2][8][4];
#pragma unroll
    for (int a = 0; a < 2; ++a)
#pragma unroll
        for (int b = 0; b < 8; ++b)
#pragma unroll
            for (int c = 0; c < 4; ++c) acc[a][b][c] = 0.f;

    for (int kt = 0; kt < 4; ++kt) {                 // 4 chunks of K=64
        const __nv_bfloat16* srcHi = (kt < 2) ? g_mhi : g_xhi;
        const __nv_bfloat16* srcLo = (kt < 2) ? g_mlo : g_xlo;
        int koff = (kt & 1) * 64;                    // col offset within 128-wide row
        int kw   = kt * 64;                          // k offset within W (256 wide)
        __syncthreads();

        // ---- A fill: pure cp.async, 8 x 16B per row per tile ----
        for (int i = tid; i < 128 * 8; i += 256) {
            int r = i >> 3, q = i & 7;
            size_t gofs = (size_t)(row0 + r) * 128 + koff + q * 8;
            cpa16(sb + S_AHI + r * APITCH + q * 16, srcHi + gofs);
            cpa16(sb + S_ALO + r * APITCH + q * 16, srcLo + gofs);
        }
        // ---- B fill: pure cp.async ----
        for (int i = tid; i < 128 * 8; i += 256) {
            int n = i >> 3, s = i & 7;
            size_t gofs = (size_t)n * 256 + kw + s * 8;
            cpa16(sb + S_BHI + n * APITCH + s * 16, g_whi + gofs);
            cpa16(sb + S_BLO + n * APITCH + s * 16, g_wlo + gofs);
        }
        CPA_COMMIT();
        CPA_WAIT0();
        __syncthreads();

        // ---- compute: 4 k16 steps ----
#pragma unroll
        for (int ks = 0; ks < 4; ++ks) {
            int lrow = (l & 7) + (l & 8);
            int lcol = ks * 16 + ((l & 16) ? 8 : 0);
            uint32_t ah[2][4], al[2][4];
#pragma unroll
            for (int mf = 0; mf < 2; ++mf) {
                int row = wr * 32 + mf * 16 + lrow;
                uint32_t addr = sb + S_AHI + row * APITCH + lcol * 2;
                ldm4(ah[mf], addr);
                ldm4(al[mf], addr + (S_ALO - S_AHI));
            }
#pragma unroll
            for (int nb = 0; nb < 4; ++nb) {
                int n = wc * 64 + nb * 16 + lrow;
                uint32_t baddr = sb + S_BHI + n * APITCH + lcol * 2;
                uint32_t bh[4], bo[4];
                ldm4(bh, baddr);
                ldm4(bo, baddr + (S_BLO - S_BHI));
#pragma unroll
                for (int mf = 0; mf < 2; ++mf) {
                    float* c0 = acc[mf][2 * nb];
                    float* c1 = acc[mf][2 * nb + 1];
                    mma16816(c0, ah[mf], bh[0], bh[2]);
                    mma16816(c1, ah[mf], bh[1], bh[3]);
                    mma16816(c0, al[mf], bh[0], bh[2]);
                    mma16816(c1, al[mf], bh[1], bh[3]);
                    mma16816(c0, ah[mf], bo[0], bo[2]);
                    mma16816(c1, ah[mf], bo[1], bo[3]);
                }
            }
        }
    }

    // ---- stage accumulators to smem (reuses tile region) ----
    __syncthreads();
    float* stag = (float*)(dsm + S_STAGE);
#pragma unroll
    for (int mf = 0; mf < 2; ++mf) {
#pragma unroll
        for (int nf = 0; nf < 8; ++nf) {
            int r = wr * 32 + mf * 16 + (l >> 2);
            int c = wc * 64 + nf * 8 + (l & 3) * 2;
            const float* cc = acc[mf][nf];
            *(float2*)(stag + r * SPITCH + c)       = make_float2(cc[0], cc[1]);
            *(float2*)(stag + (r + 8) * SPITCH + c) = make_float2(cc[2], cc[3]);
        }
    }
    __syncthreads();

    // ---- LN + ReLU: warp w handles rows w*16 .. w*16+15 ----
    const float4* biasS = (const float4*)(dsm + S_BIAS);
    const float4* gamS  = (const float4*)(dsm + S_GAM);
    const float4* betS  = (const float4*)(dsm + S_BET);
    float4 bb = biasS[l], gg = gamS[l], ee = betS[l];

    for (int r = w * 16; r < w * 16 + 16; ++r) {
        float4 v = *(const float4*)(stag + r * SPITCH + l * 4);
        v.x += bb.x; v.y += bb.y; v.z += bb.z; v.w += bb.w;
        float s = v.x + v.y + v.z + v.w;
#pragma unroll
        for (int m = 1; m < 32; m <<= 1) s += __shfl_xor_sync(0xffffffffu, s, m);
        float mu = s * (1.0f / 128.0f);
        float dx = v.x - mu, dy = v.y - mu, dz = v.z - mu, dw = v.w - mu;
        float q = dx * dx + dy * dy + dz * dz + dw * dw;
#pragma unroll
        for (int m = 1; m < 32; m <<= 1) q += __shfl_xor_sync(0xffffffffu, q, m);
        float rstd = rsqrtf(q * (1.0f / 128.0f) + 1e-5f);

        int g = row0 + r;
        if (g < N) {
            float4 o;
            o.x = fmaxf(fmaf(dx * rstd, gg.x, ee.x), 0.f);
            o.y = fmaxf(fmaf(dy * rstd, gg.y, ee.y), 0.f);
            o.z = fmaxf(fmaf(dz * rstd, gg.z, ee.z), 0.f);
            o.w = fmaxf(fmaf(dw * rstd, gg.w, ee.w), 0.f);
            *(float4*)(out + (size_t)g * 128 + l * 4) = o;
        }
    }
}

// ---------------------------------------------------------------------------
// Launch: 4 kernels (was 6) — prep, build+xprep (fused grid), pull, gemm.
// ---------------------------------------------------------------------------
extern "C" void kernel_launch(void* const* d_in, const int* in_sizes, int n_in,
                              void* d_out, int out_size) {
    const float* x      = (const float*)d_in[0];
    const void*  ei     = d_in[1];
    const float* Wl     = (const float*)d_in[2];
    const float* bl     = (const float*)d_in[3];
    const float* Wr     = (const float*)d_in[4];
    const float* gamma  = (const float*)d_in[5];
    const float* beta   = (const float*)d_in[6];
    float* out          = (float*)d_out;

    int N = in_sizes[0] / DIM;
    int E = in_sizes[1] / 2;

    cudaFuncSetAttribute(gemm_mma_kernel, cudaFuncAttributeMaxDynamicSharedMemorySize, SMEM_TOT);

    {
        int total = (N > 128 * 256) ? N : 128 * 256;
        prep_kernel<<<(total + 255) / 256, 256>>>(ei, E, N, Wl, Wr);
    }
    {
        int bb = BBLK(E);
        build_xprep_kernel<<<bb + XBLK, 256>>>(ei, x, E, N, bb);
    }
    {
        int blocks = (NPAD + 7) / 8;        // one warp per node incl. pad rows
        pull_kernel<<<blocks, 256>>>(x, N);
    }
    {
        int blocks = (N + 127) / 128;
        gemm_mma_kernel<<<blocks, 256, SMEM_TOT>>>(bl, gamma, beta, out, N);
    }
}